// round 15
// baseline (speedup 1.0000x reference)
#include <cuda_runtime.h>
#include <cuda_fp16.h>

#define NN 100000
#define EE 3200000
#define GG 100
#define HH 48

// ---------------- device scratch ----------------
__device__ int    g_degi[NN];
__device__ float  g_dis[NN];
__device__ float  g_diag[NN];
__device__ int    g_cnt[NN];
__device__ int    g_rowptr[NN + 1];
__device__ int2   g_edge[EE];          // {src, weight as half2 (broadcast) bits}, by dst
__device__ __half g_x16[NN * 16];
__device__ float2 g_T1[NN * 12];       // 48 halves per row, 8B-aligned for float2 gathers
__device__ float2 g_T2[NN * 12];
__device__ float2 g_T3[NN * 12];
__device__ float2 g_T4[NN * 12];
__device__ float2 g_hA[NN * 12];
__device__ float2 g_hB[NN * 12];

__device__ __forceinline__ __half2 b2h2(int v) {
    union { int i; __half2 h; } u; u.i = v; return u.h;
}
__device__ __forceinline__ int h2b(__half2 v) {
    union { int i; __half2 h; } u; u.h = v; return u.i;
}

// ---------------- graph preprocessing ----------------
__global__ void k_degree(const int* __restrict__ src, const int* __restrict__ dst) {
    int e = blockIdx.x * blockDim.x + threadIdx.x;
    if (e >= EE) return;
    atomicAdd(&g_degi[src[e]], 1);
    atomicAdd(&g_cnt[dst[e]], 1);
}

__global__ void k_node(const int* __restrict__ batch, const float* __restrict__ lmax) {
    int n = blockIdx.x * blockDim.x + threadIdx.x;
    if (n >= NN) return;
    float d = (float)g_degi[n];
    g_dis[n] = (d > 0.0f) ? rsqrtf(d) : 0.0f;
    g_diag[n] = 2.0f / lmax[batch[n]] - 1.0f;
}

// single-block exclusive scan of g_cnt -> g_rowptr
__global__ void k_scan() {
    __shared__ int sums[1024];
    const int tid = threadIdx.x;
    const int CH = (NN + 1023) / 1024;
    int start = tid * CH;
    int end = start + CH; if (end > NN) end = NN; if (start > NN) start = NN;
    int s = 0;
    for (int i = start; i < end; i++) s += g_cnt[i];
    sums[tid] = s;
    __syncthreads();
    for (int off = 1; off < 1024; off <<= 1) {
        int v = (tid >= off) ? sums[tid - off] : 0;
        __syncthreads();
        sums[tid] += v;
        __syncthreads();
    }
    int run = sums[tid] - s;
    for (int i = start; i < end; i++) {
        g_rowptr[i] = run;
        run += g_cnt[i];
    }
    if (tid == 1023) g_rowptr[NN] = run;
}

__global__ void k_fill(const int* __restrict__ src, const int* __restrict__ dst,
                       const float* __restrict__ lmax) {
    int e = blockIdx.x * blockDim.x + threadIdx.x;
    if (e >= EE) return;
    int s = src[e], d = dst[e];
    int pos = g_rowptr[d] + atomicAdd(&g_cnt[d], 1);
    float w = -2.0f * g_dis[s] * g_dis[d] / lmax[s / (NN / GG)];
    __half2 w2 = __half2half2(__float2half_rn(w));
    g_edge[pos] = make_int2(s, h2b(w2));
}

__global__ void k_xcast(const float* __restrict__ x) {
    int i = blockIdx.x * blockDim.x + threadIdx.x;
    if (i >= NN * 8) return;
    float2 v = reinterpret_cast<const float2*>(x)[i];
    reinterpret_cast<__half2*>(g_x16)[i] = __floats2half2_rn(v.x, v.y);
}

// ---------------- Chebyshev propagation ------------------------------------------
// F = 16: 8 lanes per node (4 nodes/warp), each lane owns one half2 column pair. (R5 form)
template <bool HASPREV>
__global__ void k_prop16(const __half2* __restrict__ tin, const __half2* __restrict__ tprev,
                         __half2* __restrict__ tout, float alpha) {
    int t = blockIdx.x * blockDim.x + threadIdx.x;
    int n = t >> 3;
    if (n >= NN) return;
    int lane = t & 7;
    int beg = g_rowptr[n], end = g_rowptr[n + 1];
    __half2 acc = __float2half2_rn(0.0f);
    int e = beg;
    for (; e + 8 <= end; e += 8) {
        int2 E[8];
#pragma unroll
        for (int j = 0; j < 8; j++) E[j] = g_edge[e + j];
        __half2 f[8];
#pragma unroll
        for (int j = 0; j < 8; j++) f[j] = tin[E[j].x * 8 + lane];
#pragma unroll
        for (int j = 0; j < 8; j++)
            acc = __hfma2(b2h2(E[j].y), f[j], acc);
    }
    for (; e < end; e++) {
        int2 E0 = g_edge[e];
        acc = __hfma2(b2h2(E0.y), tin[E0.x * 8 + lane], acc);
    }
    float2 a = __half22float2(acc);
    float dg = g_diag[n];
    float2 fs = __half22float2(tin[n * 8 + lane]);
    float rx = alpha * (dg * fs.x + a.x);
    float ry = alpha * (dg * fs.y + a.y);
    if (HASPREV) {
        float2 fp = __half22float2(tprev[n * 8 + lane]);
        rx -= fp.x; ry -= fp.y;
    }
    tout[n * 8 + lane] = __floats2half2_rn(rx, ry);
}

// F = 48: warp per node; 12 lanes x 8B per row, TWO edges per warp-instruction.
// Lanes 0-11 process even-slot edges, lanes 12-23 odd-slot; shfl-merge at end.
template <bool HASPREV>
__global__ void k_prop48(const float2* __restrict__ tin, const float2* __restrict__ tprev,
                         float2* __restrict__ tout, float alpha) {
    int n = (blockIdx.x * blockDim.x + threadIdx.x) >> 5;
    if (n >= NN) return;
    int lane = threadIdx.x & 31;
    bool act = lane < 24;
    int grp = act ? (lane >= 12 ? 1 : 0) : 0;
    int li  = act ? (lane - grp * 12) : 0;
    int beg = g_rowptr[n], end = g_rowptr[n + 1];
    __half2 a0 = __float2half2_rn(0.0f);
    __half2 a1 = __float2half2_rn(0.0f);
    int e = beg;
    for (; e + 8 <= end; e += 8) {
        int2 E[8];
#pragma unroll
        for (int j = 0; j < 8; j++) E[j] = g_edge[e + j];
        float2 f[4];
#pragma unroll
        for (int j = 0; j < 4; j++) f[j] = tin[E[2 * j + grp].x * 12 + li];
#pragma unroll
        for (int j = 0; j < 4; j++) {
            __half2 w = b2h2(E[2 * j + grp].y);
            const __half2* p = reinterpret_cast<const __half2*>(&f[j]);
            a0 = __hfma2(w, p[0], a0);
            a1 = __hfma2(w, p[1], a1);
        }
    }
    for (; e < end; e += 2) {
        int idx = e + grp;
        int2 E0;
        if (idx < end) E0 = g_edge[idx];
        else { E0.x = g_edge[e].x; E0.y = 0; }   // w = +0: contributes nothing
        float2 f0 = tin[E0.x * 12 + li];
        __half2 w = b2h2(E0.y);
        const __half2* p = reinterpret_cast<const __half2*>(&f0);
        a0 = __hfma2(w, p[0], a0);
        a1 = __hfma2(w, p[1], a1);
    }
    // merge group-1 partials into group-0 lanes
    int b0 = __shfl_down_sync(0xFFFFFFFFu, h2b(a0), 12);
    int b1 = __shfl_down_sync(0xFFFFFFFFu, h2b(a1), 12);
    if (lane < 12) {
        a0 = __hadd2(a0, b2h2(b0));
        a1 = __hadd2(a1, b2h2(b1));
        float2 A0 = __half22float2(a0);
        float2 A1 = __half22float2(a1);
        float dg = g_diag[n];
        float2 fsv = tin[n * 12 + li];
        const __half2* sp = reinterpret_cast<const __half2*>(&fsv);
        float2 s0 = __half22float2(sp[0]);
        float2 s1 = __half22float2(sp[1]);
        float r0x = alpha * (dg * s0.x + A0.x);
        float r0y = alpha * (dg * s0.y + A0.y);
        float r1x = alpha * (dg * s1.x + A1.x);
        float r1y = alpha * (dg * s1.y + A1.y);
        if (HASPREV) {
            float2 pv = tprev[n * 12 + li];
            const __half2* pp = reinterpret_cast<const __half2*>(&pv);
            float2 p0 = __half22float2(pp[0]);
            float2 p1 = __half22float2(pp[1]);
            r0x -= p0.x; r0y -= p0.y;
            r1x -= p1.x; r1y -= p1.y;
        }
        float2 outv;
        __half2* op = reinterpret_cast<__half2*>(&outv);
        op[0] = __floats2half2_rn(r0x, r0y);
        op[1] = __floats2half2_rn(r1x, r1y);
        tout[n * 12 + li] = outv;
    }
}

// ---------------- fused layer output: h = relu(b + sum_k T_k @ W[k]) ----------------
template <int FIN>
__global__ void k_mix(const __half2* __restrict__ T0, const __half2* __restrict__ T1,
                      const __half2* __restrict__ T2, const __half2* __restrict__ T3,
                      const __half2* __restrict__ T4,
                      const float* __restrict__ W, const float* __restrict__ b,
                      __half2* __restrict__ hout) {
    __shared__ __align__(16) float sW[5 * FIN * 48];
    const int tot = 5 * FIN * 48;
    for (int i = threadIdx.x; i < tot; i += blockDim.x) sW[i] = W[i];
    __syncthreads();
    int gid = blockIdx.x * blockDim.x + threadIdx.x;
    int n = gid / 12;
    int f = (gid % 12) * 4;
    if (n >= NN) return;
    const __half2* Ts[5] = {T0, T1, T2, T3, T4};
    float4 acc = *reinterpret_cast<const float4*>(&b[f]);
#pragma unroll
    for (int k = 0; k < 5; k++) {
        const __half2* T = Ts[k] + n * (FIN / 2);
        const float* wk = &sW[k * FIN * 48 + f];
#pragma unroll
        for (int i2 = 0; i2 < FIN / 2; i2++) {
            float2 v = __half22float2(T[i2]);
            float4 w0 = *reinterpret_cast<const float4*>(wk + (2 * i2) * 48);
            float4 w1 = *reinterpret_cast<const float4*>(wk + (2 * i2 + 1) * 48);
            acc.x += v.x * w0.x + v.y * w1.x;
            acc.y += v.x * w0.y + v.y * w1.y;
            acc.z += v.x * w0.z + v.y * w1.z;
            acc.w += v.x * w0.w + v.y * w1.w;
        }
    }
    acc.x = fmaxf(acc.x, 0.0f);
    acc.y = fmaxf(acc.y, 0.0f);
    acc.z = fmaxf(acc.z, 0.0f);
    acc.w = fmaxf(acc.w, 0.0f);
    hout[n * 24 + f / 2]     = __floats2half2_rn(acc.x, acc.y);
    hout[n * 24 + f / 2 + 1] = __floats2half2_rn(acc.z, acc.w);
}

// ---------------- global_add_pool + MLP head ----------------
__global__ void k_pool(const __half* __restrict__ h,
                       const float* __restrict__ fc1w, const float* __restrict__ fc1b,
                       const float* __restrict__ fc2w, const float* __restrict__ fc2b,
                       float* __restrict__ out) {
    const int g = blockIdx.x;
    const int tid = threadIdx.x;
    const int r = tid / 48, f = tid % 48;
    const int base = g * (NN / GG);
    float a = 0.0f;
    for (int n = base + r; n < base + (NN / GG); n += 10) a += __half2float(h[n * 48 + f]);
    __shared__ float red[480];
    __shared__ float pooled[48];
    __shared__ float o1[32];
    red[tid] = a;
    __syncthreads();
    if (tid < 48) {
        float s = 0.0f;
        for (int rr = 0; rr < 10; rr++) s += red[rr * 48 + tid];
        pooled[tid] = s;
    }
    __syncthreads();
    if (tid < 32) {
        float s = fc1b[tid];
        for (int i = 0; i < 48; i++) s += pooled[i] * fc1w[i * 32 + tid];
        o1[tid] = fmaxf(s, 0.0f);
    }
    __syncthreads();
    if (tid == 0) {
        float s = fc2b[0];
        for (int j = 0; j < 32; j++) s += o1[j] * fc2w[j];
        out[g] = s;
    }
}

// ---------------- host launcher ----------------
extern "C" void kernel_launch(void* const* d_in, const int* in_sizes, int n_in,
                              void* d_out, int out_size) {
    const float* x     = (const float*)d_in[0];
    const int*   ei    = (const int*)d_in[1];
    const int*   src   = ei;
    const int*   dst   = ei + EE;
    const int*   batch = (const int*)d_in[2];
    const float* lmax  = (const float*)d_in[3];
    const float* W[5]  = {(const float*)d_in[4], (const float*)d_in[6], (const float*)d_in[8],
                          (const float*)d_in[10], (const float*)d_in[12]};
    const float* B[5]  = {(const float*)d_in[5], (const float*)d_in[7], (const float*)d_in[9],
                          (const float*)d_in[11], (const float*)d_in[13]};
    const float* fc1w = (const float*)d_in[14];
    const float* fc1b = (const float*)d_in[15];
    const float* fc2w = (const float*)d_in[16];
    const float* fc2b = (const float*)d_in[17];
    float* out = (float*)d_out;

    void* p;
    cudaGetSymbolAddress(&p, g_degi); int* degi = (int*)p;
    cudaGetSymbolAddress(&p, g_cnt);  int* cnt = (int*)p;
    cudaGetSymbolAddress(&p, g_x16);  __half2* x16 = (__half2*)p;
    cudaGetSymbolAddress(&p, g_T1);   float2* T1 = (float2*)p;
    cudaGetSymbolAddress(&p, g_T2);   float2* T2 = (float2*)p;
    cudaGetSymbolAddress(&p, g_T3);   float2* T3 = (float2*)p;
    cudaGetSymbolAddress(&p, g_T4);   float2* T4 = (float2*)p;
    cudaGetSymbolAddress(&p, g_hA);   float2* hA = (float2*)p;
    cudaGetSymbolAddress(&p, g_hB);   float2* hB = (float2*)p;

    cudaMemsetAsync(degi, 0, NN * sizeof(int), 0);
    cudaMemsetAsync(cnt, 0, NN * sizeof(int), 0);
    k_degree<<<(EE + 255) / 256, 256>>>(src, dst);
    k_node<<<(NN + 255) / 256, 256>>>(batch, lmax);
    k_scan<<<1, 1024>>>();
    cudaMemsetAsync(cnt, 0, NN * sizeof(int), 0);
    k_fill<<<(EE + 255) / 256, 256>>>(src, dst, lmax);
    k_xcast<<<(NN * 8 + 255) / 256, 256>>>(x);

    const int PB = 256;
    const int pgrid48 = (NN * 32 + PB - 1) / PB;  // warp per node
    const int pgrid16 = (NN * 8 + PB - 1) / PB;   // 8 lanes per node
    const int mgrid = (NN * 12 + 255) / 256;

    // layer 1 (F_in = 16, T0 = x16) — prop16 treats T buffers as half2 rows of 8
    k_prop16<false><<<pgrid16, PB>>>(x16, nullptr, (__half2*)T1, 1.0f);
    k_prop16<true><<<pgrid16, PB>>>((__half2*)T1, x16, (__half2*)T2, 2.0f);
    k_prop16<true><<<pgrid16, PB>>>((__half2*)T2, (__half2*)T1, (__half2*)T3, 2.0f);
    k_prop16<true><<<pgrid16, PB>>>((__half2*)T3, (__half2*)T2, (__half2*)T4, 2.0f);
    k_mix<16><<<mgrid, 256>>>(x16, (__half2*)T1, (__half2*)T2, (__half2*)T3, (__half2*)T4,
                              W[0], B[0], (__half2*)hA);

    // layers 2..5 (F_in = 48), ping-pong hA <-> hB
    float2* cur = hA;
    float2* nxt = hB;
    for (int l = 1; l < 5; l++) {
        k_prop48<false><<<pgrid48, PB>>>(cur, nullptr, T1, 1.0f);
        k_prop48<true><<<pgrid48, PB>>>(T1, cur, T2, 2.0f);
        k_prop48<true><<<pgrid48, PB>>>(T2, T1, T3, 2.0f);
        k_prop48<true><<<pgrid48, PB>>>(T3, T2, T4, 2.0f);
        k_mix<48><<<mgrid, 256>>>((__half2*)cur, (__half2*)T1, (__half2*)T2, (__half2*)T3,
                                  (__half2*)T4, W[l], B[l], (__half2*)nxt);
        float2* t = cur; cur = nxt; nxt = t;
    }

    k_pool<<<GG, 480>>>((const __half*)cur, fc1w, fc1b, fc2w, fc2b, out);
}

// round 17
// speedup vs baseline: 1.5177x; 1.5177x over previous
#include <cuda_runtime.h>
#include <cuda_fp16.h>

#define NN 100000
#define EE 3200000
#define GG 100
#define HH 48

// ---------------- device scratch ----------------
__device__ int   g_degi[NN];
__device__ float g_dis[NN];
__device__ float g_diag[NN];
__device__ int   g_cnt[NN];
__device__ int   g_rowptr[NN + 1];
__device__ int2  g_edge[EE];          // {src, weight as half2 (broadcast) bits}, by dst
__device__ __half g_x16[NN * 16];
__device__ __half g_T1[NN * HH];
__device__ __half g_T2[NN * HH];
__device__ __half g_T3[NN * HH];
__device__ __half g_T4[NN * HH];
__device__ __half g_hA[NN * HH];
__device__ __half g_hB[NN * HH];

// ---------------- graph preprocessing ----------------
// degree histograms; low threads also convert x -> fp16 (independent work)
__global__ void k_degree(const int* __restrict__ src, const int* __restrict__ dst,
                         const float* __restrict__ x) {
    int e = blockIdx.x * blockDim.x + threadIdx.x;
    if (e < NN * 8) {
        float2 v = reinterpret_cast<const float2*>(x)[e];
        reinterpret_cast<__half2*>(g_x16)[e] = __floats2half2_rn(v.x, v.y);
    }
    if (e >= EE) return;
    atomicAdd(&g_degi[src[e]], 1);
    atomicAdd(&g_cnt[dst[e]], 1);
}

__global__ void k_node(const int* __restrict__ batch, const float* __restrict__ lmax) {
    int n = blockIdx.x * blockDim.x + threadIdx.x;
    if (n >= NN) return;
    float d = (float)g_degi[n];
    g_dis[n] = (d > 0.0f) ? rsqrtf(d) : 0.0f;
    g_diag[n] = 2.0f / lmax[batch[n]] - 1.0f;
}

// single-block exclusive scan of g_cnt -> g_rowptr
__global__ void k_scan() {
    __shared__ int sums[1024];
    const int tid = threadIdx.x;
    const int CH = (NN + 1023) / 1024;
    int start = tid * CH;
    int end = start + CH; if (end > NN) end = NN; if (start > NN) start = NN;
    int s = 0;
    for (int i = start; i < end; i++) s += g_cnt[i];
    sums[tid] = s;
    __syncthreads();
    for (int off = 1; off < 1024; off <<= 1) {
        int v = (tid >= off) ? sums[tid - off] : 0;
        __syncthreads();
        sums[tid] += v;
        __syncthreads();
    }
    int run = sums[tid] - s;
    for (int i = start; i < end; i++) {
        g_rowptr[i] = run;
        run += g_cnt[i];
    }
    if (tid == 1023) g_rowptr[NN] = run;
}

__global__ void k_fill(const int* __restrict__ src, const int* __restrict__ dst,
                       const float* __restrict__ lmax) {
    int e = blockIdx.x * blockDim.x + threadIdx.x;
    if (e >= EE) return;
    int s = src[e], d = dst[e];
    int pos = g_rowptr[d] + atomicAdd(&g_cnt[d], 1);
    float w = -2.0f * g_dis[s] * g_dis[d] / lmax[s / (NN / GG)];
    __half2 w2 = __half2half2(__float2half_rn(w));
    g_edge[pos] = make_int2(s, *reinterpret_cast<const int*>(&w2));
}

// ---------------- Chebyshev propagation (fp16, HFMA2, broadcast edge loads: R5) ------
// F = 16: 8 lanes per node (4 nodes/warp), each lane owns one half2 column pair.
template <bool HASPREV>
__global__ void k_prop16(const __half2* __restrict__ tin, const __half2* __restrict__ tprev,
                         __half2* __restrict__ tout, float alpha) {
    int t = blockIdx.x * blockDim.x + threadIdx.x;
    int n = t >> 3;
    if (n >= NN) return;
    int lane = t & 7;
    int beg = g_rowptr[n], end = g_rowptr[n + 1];
    __half2 acc = __float2half2_rn(0.0f);
    int e = beg;
    for (; e + 8 <= end; e += 8) {
        int2 E[8];
#pragma unroll
        for (int j = 0; j < 8; j++) E[j] = g_edge[e + j];
        __half2 f[8];
#pragma unroll
        for (int j = 0; j < 8; j++) f[j] = tin[E[j].x * 8 + lane];
#pragma unroll
        for (int j = 0; j < 8; j++)
            acc = __hfma2(*reinterpret_cast<const __half2*>(&E[j].y), f[j], acc);
    }
    for (; e < end; e++) {
        int2 E0 = g_edge[e];
        __half2 f0 = tin[E0.x * 8 + lane];
        acc = __hfma2(*reinterpret_cast<const __half2*>(&E0.y), f0, acc);
    }
    float2 a = __half22float2(acc);
    float dg = g_diag[n];
    float2 fs = __half22float2(tin[n * 8 + lane]);
    float rx = alpha * (dg * fs.x + a.x);
    float ry = alpha * (dg * fs.y + a.y);
    if (HASPREV) {
        float2 fp = __half22float2(tprev[n * 8 + lane]);
        rx -= fp.x; ry -= fp.y;
    }
    tout[n * 8 + lane] = __floats2half2_rn(rx, ry);
}

// F = 48: warp per node, lanes 0..23 own half2 column pairs (96B rows, unpadded).
template <bool HASPREV>
__global__ void k_prop48(const __half2* __restrict__ tin, const __half2* __restrict__ tprev,
                         __half2* __restrict__ tout, float alpha) {
    int n = (blockIdx.x * blockDim.x + threadIdx.x) >> 5;
    if (n >= NN) return;
    int lane = threadIdx.x & 31;
    bool act = lane < 24;
    int li = act ? lane : 0;
    int beg = g_rowptr[n], end = g_rowptr[n + 1];
    __half2 acc = __float2half2_rn(0.0f);
    int e = beg;
    for (; e + 8 <= end; e += 8) {
        int2 E[8];
#pragma unroll
        for (int j = 0; j < 8; j++) E[j] = g_edge[e + j];
        __half2 f[8];
#pragma unroll
        for (int j = 0; j < 8; j++) f[j] = tin[E[j].x * 24 + li];
#pragma unroll
        for (int j = 0; j < 8; j++)
            acc = __hfma2(*reinterpret_cast<const __half2*>(&E[j].y), f[j], acc);
    }
    for (; e < end; e++) {
        int2 E0 = g_edge[e];
        __half2 f0 = tin[E0.x * 24 + li];
        acc = __hfma2(*reinterpret_cast<const __half2*>(&E0.y), f0, acc);
    }
    if (act) {
        float2 a = __half22float2(acc);
        float dg = g_diag[n];
        float2 fs = __half22float2(tin[n * 24 + lane]);
        float rx = alpha * (dg * fs.x + a.x);
        float ry = alpha * (dg * fs.y + a.y);
        if (HASPREV) {
            float2 fp = __half22float2(tprev[n * 24 + lane]);
            rx -= fp.x; ry -= fp.y;
        }
        tout[n * 24 + lane] = __floats2half2_rn(rx, ry);
    }
}

// ---------------- fused layer output: h = relu(b + sum_k T_k @ W[k]) ----------------
// NPT items per thread (grid-stride) -> 1/NPT as many blocks -> 1/NPT weight smem fills.
template <int FIN, int NPT>
__global__ void k_mix(const __half2* __restrict__ T0, const __half2* __restrict__ T1,
                      const __half2* __restrict__ T2, const __half2* __restrict__ T3,
                      const __half2* __restrict__ T4,
                      const float* __restrict__ W, const float* __restrict__ b,
                      __half2* __restrict__ hout) {
    __shared__ __align__(16) float sW[5 * FIN * 48];
    const int tot = 5 * FIN * 48;
    for (int i = threadIdx.x; i < tot; i += blockDim.x) sW[i] = W[i];
    __syncthreads();
    const int stride = gridDim.x * blockDim.x;
    int idx = blockIdx.x * blockDim.x + threadIdx.x;
    const __half2* Ts[5] = {T0, T1, T2, T3, T4};
#pragma unroll
    for (int it = 0; it < NPT; it++, idx += stride) {
        int n = idx / 12;
        int f = (idx % 12) * 4;
        if (n >= NN) break;
        float4 acc = *reinterpret_cast<const float4*>(&b[f]);
#pragma unroll
        for (int k = 0; k < 5; k++) {
            const __half2* T = Ts[k] + n * (FIN / 2);
            const float* wk = &sW[k * FIN * 48 + f];
#pragma unroll
            for (int i2 = 0; i2 < FIN / 2; i2++) {
                float2 v = __half22float2(T[i2]);
                float4 w0 = *reinterpret_cast<const float4*>(wk + (2 * i2) * 48);
                float4 w1 = *reinterpret_cast<const float4*>(wk + (2 * i2 + 1) * 48);
                acc.x += v.x * w0.x + v.y * w1.x;
                acc.y += v.x * w0.y + v.y * w1.y;
                acc.z += v.x * w0.z + v.y * w1.z;
                acc.w += v.x * w0.w + v.y * w1.w;
            }
        }
        acc.x = fmaxf(acc.x, 0.0f);
        acc.y = fmaxf(acc.y, 0.0f);
        acc.z = fmaxf(acc.z, 0.0f);
        acc.w = fmaxf(acc.w, 0.0f);
        hout[n * 24 + f / 2]     = __floats2half2_rn(acc.x, acc.y);
        hout[n * 24 + f / 2 + 1] = __floats2half2_rn(acc.z, acc.w);
    }
}

// ---------------- global_add_pool + MLP head ----------------
__global__ void k_pool(const __half* __restrict__ h,
                       const float* __restrict__ fc1w, const float* __restrict__ fc1b,
                       const float* __restrict__ fc2w, const float* __restrict__ fc2b,
                       float* __restrict__ out) {
    const int g = blockIdx.x;
    const int tid = threadIdx.x;
    const int r = tid / 48, f = tid % 48;
    const int base = g * (NN / GG);
    float a = 0.0f;
    for (int n = base + r; n < base + (NN / GG); n += 10) a += __half2float(h[n * 48 + f]);
    __shared__ float red[480];
    __shared__ float pooled[48];
    __shared__ float o1[32];
    red[tid] = a;
    __syncthreads();
    if (tid < 48) {
        float s = 0.0f;
        for (int rr = 0; rr < 10; rr++) s += red[rr * 48 + tid];
        pooled[tid] = s;
    }
    __syncthreads();
    if (tid < 32) {
        float s = fc1b[tid];
        for (int i = 0; i < 48; i++) s += pooled[i] * fc1w[i * 32 + tid];
        o1[tid] = fmaxf(s, 0.0f);
    }
    __syncthreads();
    if (tid == 0) {
        float s = fc2b[0];
        for (int j = 0; j < 32; j++) s += o1[j] * fc2w[j];
        out[g] = s;
    }
}

// ---------------- host launcher ----------------
extern "C" void kernel_launch(void* const* d_in, const int* in_sizes, int n_in,
                              void* d_out, int out_size) {
    const float* x     = (const float*)d_in[0];
    const int*   ei    = (const int*)d_in[1];
    const int*   src   = ei;
    const int*   dst   = ei + EE;
    const int*   batch = (const int*)d_in[2];
    const float* lmax  = (const float*)d_in[3];
    const float* W[5]  = {(const float*)d_in[4], (const float*)d_in[6], (const float*)d_in[8],
                          (const float*)d_in[10], (const float*)d_in[12]};
    const float* B[5]  = {(const float*)d_in[5], (const float*)d_in[7], (const float*)d_in[9],
                          (const float*)d_in[11], (const float*)d_in[13]};
    const float* fc1w = (const float*)d_in[14];
    const float* fc1b = (const float*)d_in[15];
    const float* fc2w = (const float*)d_in[16];
    const float* fc2b = (const float*)d_in[17];
    float* out = (float*)d_out;

    void* p;
    cudaGetSymbolAddress(&p, g_degi); int* degi = (int*)p;
    cudaGetSymbolAddress(&p, g_cnt);  int* cnt = (int*)p;
    cudaGetSymbolAddress(&p, g_x16);  __half2* x16 = (__half2*)p;
    cudaGetSymbolAddress(&p, g_T1);   __half2* T1 = (__half2*)p;
    cudaGetSymbolAddress(&p, g_T2);   __half2* T2 = (__half2*)p;
    cudaGetSymbolAddress(&p, g_T3);   __half2* T3 = (__half2*)p;
    cudaGetSymbolAddress(&p, g_T4);   __half2* T4 = (__half2*)p;
    cudaGetSymbolAddress(&p, g_hA);   __half2* hA = (__half2*)p;
    cudaGetSymbolAddress(&p, g_hB);   __half2* hB = (__half2*)p;

    cudaMemsetAsync(degi, 0, NN * sizeof(int), 0);
    cudaMemsetAsync(cnt, 0, NN * sizeof(int), 0);
    k_degree<<<(EE + 255) / 256, 256>>>(src, dst, x);
    k_node<<<(NN + 255) / 256, 256>>>(batch, lmax);
    k_scan<<<1, 1024>>>();
    cudaMemsetAsync(cnt, 0, NN * sizeof(int), 0);
    k_fill<<<(EE + 255) / 256, 256>>>(src, dst, lmax);

    const int PB = 256;
    const int pgrid48 = (NN * 32 + PB - 1) / PB;  // warp per node
    const int pgrid16 = (NN * 8 + PB - 1) / PB;   // 8 lanes per node
    const int NPT = 4;
    const int mgrid = (NN * 12 + 256 * NPT - 1) / (256 * NPT);  // ~1172 blocks

    // layer 1 (F_in = 16, T0 = x16)
    k_prop16<false><<<pgrid16, PB>>>(x16, nullptr, T1, 1.0f);
    k_prop16<true><<<pgrid16, PB>>>(T1, x16, T2, 2.0f);
    k_prop16<true><<<pgrid16, PB>>>(T2, T1, T3, 2.0f);
    k_prop16<true><<<pgrid16, PB>>>(T3, T2, T4, 2.0f);
    k_mix<16, NPT><<<mgrid, 256>>>(x16, T1, T2, T3, T4, W[0], B[0], hA);

    // layers 2..5 (F_in = 48), ping-pong hA <-> hB
    __half2* cur = hA;
    __half2* nxt = hB;
    for (int l = 1; l < 5; l++) {
        k_prop48<false><<<pgrid48, PB>>>(cur, nullptr, T1, 1.0f);
        k_prop48<true><<<pgrid48, PB>>>(T1, cur, T2, 2.0f);
        k_prop48<true><<<pgrid48, PB>>>(T2, T1, T3, 2.0f);
        k_prop48<true><<<pgrid48, PB>>>(T3, T2, T4, 2.0f);
        k_mix<48, NPT><<<mgrid, 256>>>(cur, T1, T2, T3, T4, W[l], B[l], nxt);
        __half2* t = cur; cur = nxt; nxt = t;
    }

    k_pool<<<GG, 480>>>((const __half*)cur, fc1w, fc1b, fc2w, fc2b, out);
}